// round 3
// baseline (speedup 1.0000x reference)
#include <cuda_runtime.h>
#include <math.h>

// Problem constants (fixed by the dataset)
#define Bq   2
#define Nc   6
#define Cc   256
#define Mq   900
#define EPSF 1e-5f

// Per-level H, W
#define H0 116
#define W0 200
#define H1 58
#define W1 100
#define H2 29
#define W2 50
#define H3 15
#define W3 25

// Bilinear gather of one channel, fully predicated. coff = channel plane offset
// within this camera's feature block (c * H * W).
template <int H, int W>
__device__ __forceinline__ float samp1(const float* __restrict__ base, int coff,
                                       float x0f, float y0f,
                                       float w00, float w10,
                                       float w01, float w11)
{
    bool bx0 = (x0f >= 0.0f)  & (x0f <= (float)(W - 1));
    bool bx1 = (x0f >= -1.0f) & (x0f <= (float)(W - 2));
    bool by0 = (y0f >= 0.0f)  & (y0f <= (float)(H - 1));
    bool by1 = (y0f >= -1.0f) & (y0f <= (float)(H - 2));

    int xi = (int)fmaxf(fminf(x0f, 1.0e8f), -1.0e8f);
    int yi = (int)fmaxf(fminf(y0f, 1.0e8f), -1.0e8f);

    const float* p = base + coff + yi * W + xi;

    float v = 0.0f;
    if (by0 & bx0) v += w00 * __ldg(p);
    if (by0 & bx1) v += w10 * __ldg(p + 1);
    if (by1 & bx0) v += w01 * __ldg(p + W);
    if (by1 & bx1) v += w11 * __ldg(p + W + 1);
    return v;
}

__global__ void zero_out_kernel(float* __restrict__ out)
{
    int i = blockIdx.x * 256 + threadIdx.x;   // grid sized exactly to B*M*C
    out[i] = 0.0f;
}

// One block per (b, m, n): 256 threads = 256 channels, single camera.
__global__ void __launch_bounds__(Cc)
feature_sampler_kernel(const float* __restrict__ f0,
                       const float* __restrict__ f1,
                       const float* __restrict__ f2,
                       const float* __restrict__ f3,
                       const float* __restrict__ refp,   // (B, M, 3)
                       const float* __restrict__ l2i,    // (B, N, 4, 4)
                       float* __restrict__ out)          // (B, M, C)
{
    int bid = blockIdx.x;          // 0 .. B*M*N-1
    int n   = bid % Nc;
    int bm  = bid / Nc;
    int b   = bm / Mq;
    int m   = bm - b * Mq;
    int c   = threadIdx.x;

    const float* rp = refp + bm * 3;
    float rx = rp[0] * 122.4f - 61.2f;
    float ry = rp[1] * 122.4f - 61.2f;
    float rz = rp[2] * 20.0f  - 10.0f;

    // All 6 cameras' z: needed for the normalization count.
    const float* Mb = l2i + b * Nc * 16;
    float cnt = 0.0f;
    float myc0 = 0.0f, myc1 = 0.0f, myc2 = -1.0f;
    #pragma unroll
    for (int k = 0; k < Nc; k++) {
        const float* Mt = Mb + k * 16;
        float z = Mt[8] * rx + Mt[9] * ry + Mt[10] * rz + Mt[11];
        cnt += (z > EPSF) ? 1.0f : 0.0f;
        if (k == n) {
            myc2 = z;
            myc0 = Mt[0] * rx + Mt[1] * ry + Mt[2] * rz + Mt[3];
            myc1 = Mt[4] * rx + Mt[5] * ry + Mt[6] * rz + Mt[7];
        }
    }

    if (!(myc2 > EPSF)) return;    // this camera contributes nothing

    float rcp = __fdividef(1.0f, myc2 + EPSF);
    // grid-sample normalization cancels: pixel coord = p - 0.5 at EVERY level
    float x = myc0 * rcp - 0.5f;
    float y = myc1 * rcp - 0.5f;
    float x0f = floorf(x);
    float y0f = floorf(y);
    float wx1 = x - x0f, wx0 = 1.0f - wx1;
    float wy1 = y - y0f, wy0 = 1.0f - wy1;
    float w00 = wx0 * wy0, w10 = wx1 * wy0;
    float w01 = wx0 * wy1, w11 = wx1 * wy1;

    int bn = b * Nc + n;
    float s = 0.0f;
    s += samp1<H0, W0>(f0 + bn * (Cc * H0 * W0), c * (H0 * W0), x0f, y0f, w00, w10, w01, w11);
    s += samp1<H1, W1>(f1 + bn * (Cc * H1 * W1), c * (H1 * W1), x0f, y0f, w00, w10, w01, w11);
    s += samp1<H2, W2>(f2 + bn * (Cc * H2 * W2), c * (H2 * W2), x0f, y0f, w00, w10, w01, w11);
    s += samp1<H3, W3>(f3 + bn * (Cc * H3 * W3), c * (H3 * W3), x0f, y0f, w00, w10, w01, w11);

    float contrib = 0.25f * s * __fdividef(1.0f, cnt + EPSF);
    atomicAdd(out + bm * Cc + c, contrib);
}

extern "C" void kernel_launch(void* const* d_in, const int* in_sizes, int n_in,
                              void* d_out, int out_size)
{
    const float* f0   = (const float*)d_in[0];
    const float* f1   = (const float*)d_in[1];
    const float* f2   = (const float*)d_in[2];
    const float* f3   = (const float*)d_in[3];
    const float* refp = (const float*)d_in[4];
    const float* l2i  = (const float*)d_in[5];
    float* out = (float*)d_out;

    zero_out_kernel<<<Bq * Mq, Cc>>>(out);
    feature_sampler_kernel<<<Bq * Mq * Nc, Cc>>>(f0, f1, f2, f3, refp, l2i, out);
}

// round 4
// speedup vs baseline: 1.5219x; 1.5219x over previous
#include <cuda_runtime.h>
#include <math.h>

// Problem constants (fixed by the dataset)
#define Bq   2
#define Nc   6
#define Cc   256
#define Mq   900
#define EPSF 1e-5f

// Per-level H, W
#define H0 116
#define W0 200
#define H1 58
#define W1 100
#define H2 29
#define W2 50
#define H3 15
#define W3 25

__device__ __forceinline__ float pick4(float4 q, int i)
{
    float r = q.w;
    r = (i == 2) ? q.z : r;
    r = (i == 1) ? q.y : r;
    r = (i == 0) ? q.x : r;
    return r;
}

__device__ __forceinline__ float pick2(float2 q, int i)
{
    return (i == 0) ? q.x : q.y;
}

// Level sampler using LDG.128: requires W % 4 == 0 and (H*W) % 4 == 0 so every
// channel plane and row is 16B-aligned. One float4 per row covers both
// x-corners except when x0 % 4 == 3 (rare predicated scalar spill).
template <int H, int W>
__device__ __forceinline__ float samp_v4(const float* __restrict__ plane,
                                         int xi, int yi,
                                         bool bx0, bool bx1, bool by0, bool by1,
                                         float w00, float w10, float w01, float w11)
{
    int a = xi & ~3;
    a = (a < 0) ? 0 : a;
    a = (a > W - 4) ? (W - 4) : a;
    int  i0 = xi - a;            // in [-1, 3]; -1 only when bx0 is false
    bool sp = (i0 >= 3);         // x1 column spills out of the float4
    bool anyx = bx0 | bx1;

    const float* r0 = plane + yi * W + a;
    float v = 0.0f;
    if (by0 & anyx) {
        float4 q = __ldg((const float4*)r0);
        if (bx0)       v += w00 * pick4(q, i0);
        if (bx1 & !sp) v += w10 * pick4(q, i0 + 1);
    }
    if (by1 & anyx) {
        float4 q = __ldg((const float4*)(r0 + W));
        if (bx0)       v += w01 * pick4(q, i0);
        if (bx1 & !sp) v += w11 * pick4(q, i0 + 1);
    }
    if (sp & bx1) {
        const float* px1 = plane + yi * W + xi + 1;
        if (by0) v += w10 * __ldg(px1);
        if (by1) v += w11 * __ldg(px1 + W);
    }
    return v;
}

// Level sampler using LDG.64: requires W % 2 == 0 and (H*W) % 2 == 0.
template <int H, int W>
__device__ __forceinline__ float samp_v2(const float* __restrict__ plane,
                                         int xi, int yi,
                                         bool bx0, bool bx1, bool by0, bool by1,
                                         float w00, float w10, float w01, float w11)
{
    int a = xi & ~1;
    a = (a < 0) ? 0 : a;
    a = (a > W - 2) ? (W - 2) : a;
    int  i0 = xi - a;            // in [-1, 1]
    bool sp = (i0 >= 1);         // x1 spills when x0 is odd
    bool anyx = bx0 | bx1;

    const float* r0 = plane + yi * W + a;
    float v = 0.0f;
    if (by0 & anyx) {
        float2 q = __ldg((const float2*)r0);
        if (bx0)       v += w00 * pick2(q, i0);
        if (bx1 & !sp) v += w10 * pick2(q, i0 + 1);
    }
    if (by1 & anyx) {
        float2 q = __ldg((const float2*)(r0 + W));
        if (bx0)       v += w01 * pick2(q, i0);
        if (bx1 & !sp) v += w11 * pick2(q, i0 + 1);
    }
    if (sp & bx1) {
        const float* px1 = plane + yi * W + xi + 1;
        if (by0) v += w10 * __ldg(px1);
        if (by1) v += w11 * __ldg(px1 + W);
    }
    return v;
}

// Scalar fallback (f3: odd plane stride, no lane-uniform alignment possible).
template <int H, int W>
__device__ __forceinline__ float samp_s(const float* __restrict__ plane,
                                        int xi, int yi,
                                        bool bx0, bool bx1, bool by0, bool by1,
                                        float w00, float w10, float w01, float w11)
{
    const float* p = plane + yi * W + xi;
    float v = 0.0f;
    if (by0 & bx0) v += w00 * __ldg(p);
    if (by0 & bx1) v += w10 * __ldg(p + 1);
    if (by1 & bx0) v += w01 * __ldg(p + W);
    if (by1 & bx1) v += w11 * __ldg(p + W + 1);
    return v;
}

__global__ void __launch_bounds__(Cc)
feature_sampler_kernel(const float* __restrict__ f0,
                       const float* __restrict__ f1,
                       const float* __restrict__ f2,
                       const float* __restrict__ f3,
                       const float* __restrict__ refp,   // (B, M, 3)
                       const float* __restrict__ l2i,    // (B, N, 4, 4)
                       float* __restrict__ out)          // (B, M, C)
{
    int bm = blockIdx.x;           // 0 .. B*M-1
    int b  = bm / Mq;
    int c  = threadIdx.x;          // channel

    const float* rp = refp + bm * 3;
    float rx = rp[0] * 122.4f - 61.2f;
    float ry = rp[1] * 122.4f - 61.2f;
    float rz = rp[2] * 20.0f  - 10.0f;

    float acc = 0.0f;
    float cnt = 0.0f;

    #pragma unroll
    for (int n = 0; n < Nc; n++) {
        const float* Mt = l2i + (b * Nc + n) * 16;
        float c0 = Mt[0] * rx + Mt[1] * ry + Mt[2]  * rz + Mt[3];
        float c1 = Mt[4] * rx + Mt[5] * ry + Mt[6]  * rz + Mt[7];
        float c2 = Mt[8] * rx + Mt[9] * ry + Mt[10] * rz + Mt[11];

        if (!(c2 > EPSF)) continue;   // camera invalid: contributes nothing
        cnt += 1.0f;

        float rcp = __fdividef(1.0f, c2 + EPSF);
        // grid-sample normalization cancels: pixel coord = p - 0.5 at EVERY level
        float x = c0 * rcp - 0.5f;
        float y = c1 * rcp - 0.5f;
        float x0f = floorf(x);
        float y0f = floorf(y);
        float wx1 = x - x0f, wx0 = 1.0f - wx1;
        float wy1 = y - y0f, wy0 = 1.0f - wy1;
        float w00 = wx0 * wy0, w10 = wx1 * wy0;
        float w01 = wx0 * wy1, w11 = wx1 * wy1;

        int xi = (int)fmaxf(fminf(x0f, 1.0e8f), -1.0e8f);
        int yi = (int)fmaxf(fminf(y0f, 1.0e8f), -1.0e8f);

        int bn = b * Nc + n;
        float s = 0.0f;

        // level 0 (116 x 200): float4 path
        {
            bool bx0 = (x0f >= 0.0f)  & (x0f <= (float)(W0 - 1));
            bool bx1 = (x0f >= -1.0f) & (x0f <= (float)(W0 - 2));
            bool by0 = (y0f >= 0.0f)  & (y0f <= (float)(H0 - 1));
            bool by1 = (y0f >= -1.0f) & (y0f <= (float)(H0 - 2));
            const float* plane = f0 + ((long long)(bn * Cc + c)) * (H0 * W0);
            s += samp_v4<H0, W0>(plane, xi, yi, bx0, bx1, by0, by1, w00, w10, w01, w11);
        }
        // level 1 (58 x 100): float4 path
        {
            bool bx0 = (x0f >= 0.0f)  & (x0f <= (float)(W1 - 1));
            bool bx1 = (x0f >= -1.0f) & (x0f <= (float)(W1 - 2));
            bool by0 = (y0f >= 0.0f)  & (y0f <= (float)(H1 - 1));
            bool by1 = (y0f >= -1.0f) & (y0f <= (float)(H1 - 2));
            const float* plane = f1 + ((long long)(bn * Cc + c)) * (H1 * W1);
            s += samp_v4<H1, W1>(plane, xi, yi, bx0, bx1, by0, by1, w00, w10, w01, w11);
        }
        // level 2 (29 x 50): float2 path
        {
            bool bx0 = (x0f >= 0.0f)  & (x0f <= (float)(W2 - 1));
            bool bx1 = (x0f >= -1.0f) & (x0f <= (float)(W2 - 2));
            bool by0 = (y0f >= 0.0f)  & (y0f <= (float)(H2 - 1));
            bool by1 = (y0f >= -1.0f) & (y0f <= (float)(H2 - 2));
            const float* plane = f2 + ((long long)(bn * Cc + c)) * (H2 * W2);
            s += samp_v2<H2, W2>(plane, xi, yi, bx0, bx1, by0, by1, w00, w10, w01, w11);
        }
        // level 3 (15 x 25): scalar path (odd plane stride)
        {
            bool bx0 = (x0f >= 0.0f)  & (x0f <= (float)(W3 - 1));
            bool bx1 = (x0f >= -1.0f) & (x0f <= (float)(W3 - 2));
            bool by0 = (y0f >= 0.0f)  & (y0f <= (float)(H3 - 1));
            bool by1 = (y0f >= -1.0f) & (y0f <= (float)(H3 - 2));
            const float* plane = f3 + ((long long)(bn * Cc + c)) * (H3 * W3);
            s += samp_s<H3, W3>(plane, xi, yi, bx0, bx1, by0, by1, w00, w10, w01, w11);
        }

        acc += 0.25f * s;
    }

    out[bm * Cc + c] = acc * __fdividef(1.0f, cnt + EPSF);
}

extern "C" void kernel_launch(void* const* d_in, const int* in_sizes, int n_in,
                              void* d_out, int out_size)
{
    const float* f0   = (const float*)d_in[0];
    const float* f1   = (const float*)d_in[1];
    const float* f2   = (const float*)d_in[2];
    const float* f3   = (const float*)d_in[3];
    const float* refp = (const float*)d_in[4];
    const float* l2i  = (const float*)d_in[5];
    float* out = (float*)d_out;

    feature_sampler_kernel<<<Bq * Mq, Cc>>>(f0, f1, f2, f3, refp, l2i, out);
}

// round 5
// speedup vs baseline: 1.7456x; 1.1470x over previous
#include <cuda_runtime.h>
#include <math.h>

// Problem constants (fixed by the dataset)
#define Bq   2
#define Nc   6
#define Cc   256
#define Mq   900
#define EPSF 1e-5f

// Per-level H, W
#define H0 116
#define W0 200
#define H1 58
#define W1 100
#define H2 29
#define W2 50
#define H3 15
#define W3 25

__device__ __forceinline__ float pick4(float4 q, int i)
{
    float r = q.w;
    r = (i == 2) ? q.z : r;
    r = (i == 1) ? q.y : r;
    r = (i == 0) ? q.x : r;
    return r;
}
__device__ __forceinline__ float pick2(float2 q, int i)
{
    return (i == 0) ? q.x : q.y;
}

// ---- Phase-1 metadata builder (runs on ONE thread per camera) ----
// V = vector width (4, 2, or 1). Produces:
//   off   : camera+pixel offset of the (aligned) load base within level tensor
//   i0    : lane selector within the vector for x0
//   spo   : offset of the x1 spill column (V>1 only)
//   flags : V>1: b0 row0-vec load, b1 row1-vec load, b2 use-x0, b3 use-x1-in-vec,
//                b4 spill-row0, b5 spill-row1
//           V=1: b0 q00, b1 q10, b2 q01, b3 q11
template <int H, int W, int V>
__device__ __forceinline__ void mk_meta(int bnC, float x0f, float y0f,
                                        int xi, int yi,
                                        int& off, int& i0o, int& spo, int& flags)
{
    bool bx0 = (x0f >= 0.0f)  & (x0f <= (float)(W - 1));
    bool bx1 = (x0f >= -1.0f) & (x0f <= (float)(W - 2));
    bool by0 = (y0f >= 0.0f)  & (y0f <= (float)(H - 1));
    bool by1 = (y0f >= -1.0f) & (y0f <= (float)(H - 2));

    if (V == 1) {
        off   = bnC * (H * W) + yi * W + xi;
        flags = ((by0 & bx0) ? 1 : 0) | ((by0 & bx1) ? 2 : 0)
              | ((by1 & bx0) ? 4 : 0) | ((by1 & bx1) ? 8 : 0);
        i0o = 0; spo = 0;
    } else {
        int a = xi & ~(V - 1);
        a = (a < 0) ? 0 : a;
        a = (a > W - V) ? (W - V) : a;
        int  i0  = xi - a;
        bool sp  = (i0 >= V - 1);
        bool bxv = bx1 & !sp;
        bool anyx = bx0 | bxv;
        bool spu  = bx1 & sp;
        int f = 0;
        f |= (by0 & anyx) ? 1  : 0;
        f |= (by1 & anyx) ? 2  : 0;
        f |= bx0          ? 4  : 0;
        f |= bxv          ? 8  : 0;
        f |= (spu & by0)  ? 16 : 0;
        f |= (spu & by1)  ? 32 : 0;
        flags = f;
        off = bnC * (H * W) + yi * W + a;
        i0o = i0;
        spo = bnC * (H * W) + yi * W + xi + 1;
    }
}

// ---- Phase-2 gather (per thread, all control values warp-uniform) ----
template <int H, int W, int V>
__device__ __forceinline__ float use_meta(const float* __restrict__ f, int c,
                                          int off, int i0, int spo, int flags,
                                          float w00, float w10, float w01, float w11)
{
    float v = 0.0f;
    const float* p = f + c * (H * W) + off;
    if (V == 4) {
        if (flags & 1) {
            float4 q = __ldg((const float4*)p);
            if (flags & 4) v += w00 * pick4(q, i0);
            if (flags & 8) v += w10 * pick4(q, i0 + 1);
        }
        if (flags & 2) {
            float4 q = __ldg((const float4*)(p + W));
            if (flags & 4) v += w01 * pick4(q, i0);
            if (flags & 8) v += w11 * pick4(q, i0 + 1);
        }
        if (flags & 16) v += w10 * __ldg(f + c * (H * W) + spo);
        if (flags & 32) v += w11 * __ldg(f + c * (H * W) + spo + W);
    } else if (V == 2) {
        if (flags & 1) {
            float2 q = __ldg((const float2*)p);
            if (flags & 4) v += w00 * pick2(q, i0);
            if (flags & 8) v += w10 * pick2(q, i0 + 1);
        }
        if (flags & 2) {
            float2 q = __ldg((const float2*)(p + W));
            if (flags & 4) v += w01 * pick2(q, i0);
            if (flags & 8) v += w11 * pick2(q, i0 + 1);
        }
        if (flags & 16) v += w10 * __ldg(f + c * (H * W) + spo);
        if (flags & 32) v += w11 * __ldg(f + c * (H * W) + spo + W);
    } else {
        if (flags & 1) v += w00 * __ldg(p);
        if (flags & 2) v += w10 * __ldg(p + 1);
        if (flags & 4) v += w01 * __ldg(p + W);
        if (flags & 8) v += w11 * __ldg(p + W + 1);
    }
    return v;
}

__global__ void __launch_bounds__(Cc)
feature_sampler_kernel(const float* __restrict__ f0,
                       const float* __restrict__ f1,
                       const float* __restrict__ f2,
                       const float* __restrict__ f3,
                       const float* __restrict__ refp,   // (B, M, 3)
                       const float* __restrict__ l2i,    // (B, N, 4, 4)
                       float* __restrict__ out)          // (B, M, C)
{
    __shared__ int   s_valid[Nc];
    __shared__ float s_w[Nc][4];
    __shared__ int   s_off[Nc][4];
    __shared__ int   s_i0[Nc][4];
    __shared__ int   s_spo[Nc][4];
    __shared__ int   s_flags[Nc][4];

    int bm = blockIdx.x;           // 0 .. B*M-1
    int b  = bm / Mq;
    int c  = threadIdx.x;          // channel

    // ---------------- Phase 1: per-camera metadata (threads 0..5) ----------
    if (c < Nc) {
        int n = c;
        const float* rp = refp + bm * 3;
        float rx = rp[0] * 122.4f - 61.2f;
        float ry = rp[1] * 122.4f - 61.2f;
        float rz = rp[2] * 20.0f  - 10.0f;

        const float* Mt = l2i + (b * Nc + n) * 16;
        float c0 = Mt[0] * rx + Mt[1] * ry + Mt[2]  * rz + Mt[3];
        float c1 = Mt[4] * rx + Mt[5] * ry + Mt[6]  * rz + Mt[7];
        float c2 = Mt[8] * rx + Mt[9] * ry + Mt[10] * rz + Mt[11];

        bool valid = (c2 > EPSF);
        s_valid[n] = valid ? 1 : 0;

        if (valid) {
            float rcp = __fdividef(1.0f, c2 + EPSF);
            // grid-sample normalization cancels: pixel = p - 0.5 at EVERY level
            float x = c0 * rcp - 0.5f;
            float y = c1 * rcp - 0.5f;
            float x0f = floorf(x);
            float y0f = floorf(y);
            float wx1 = x - x0f, wx0 = 1.0f - wx1;
            float wy1 = y - y0f, wy0 = 1.0f - wy1;
            s_w[n][0] = wx0 * wy0;
            s_w[n][1] = wx1 * wy0;
            s_w[n][2] = wx0 * wy1;
            s_w[n][3] = wx1 * wy1;

            int xi = (int)fmaxf(fminf(x0f, 1.0e8f), -1.0e8f);
            int yi = (int)fmaxf(fminf(y0f, 1.0e8f), -1.0e8f);
            int bnC = (b * Nc + n) * Cc;

            mk_meta<H0, W0, 4>(bnC, x0f, y0f, xi, yi,
                               s_off[n][0], s_i0[n][0], s_spo[n][0], s_flags[n][0]);
            mk_meta<H1, W1, 4>(bnC, x0f, y0f, xi, yi,
                               s_off[n][1], s_i0[n][1], s_spo[n][1], s_flags[n][1]);
            mk_meta<H2, W2, 2>(bnC, x0f, y0f, xi, yi,
                               s_off[n][2], s_i0[n][2], s_spo[n][2], s_flags[n][2]);
            mk_meta<H3, W3, 1>(bnC, x0f, y0f, xi, yi,
                               s_off[n][3], s_i0[n][3], s_spo[n][3], s_flags[n][3]);
        } else {
            s_flags[n][0] = 0; s_flags[n][1] = 0;
            s_flags[n][2] = 0; s_flags[n][3] = 0;
        }
    }
    __syncthreads();

    // ---------------- Phase 2: gathers (all 256 threads) -------------------
    float acc = 0.0f;
    int cnt = 0;

    #pragma unroll
    for (int n = 0; n < Nc; n++) {
        int valid = s_valid[n];
        cnt += valid;
        if (!valid) continue;      // warp-uniform branch

        float w00 = s_w[n][0], w10 = s_w[n][1];
        float w01 = s_w[n][2], w11 = s_w[n][3];

        float s = 0.0f;
        s += use_meta<H0, W0, 4>(f0, c, s_off[n][0], s_i0[n][0], s_spo[n][0],
                                 s_flags[n][0], w00, w10, w01, w11);
        s += use_meta<H1, W1, 4>(f1, c, s_off[n][1], s_i0[n][1], s_spo[n][1],
                                 s_flags[n][1], w00, w10, w01, w11);
        s += use_meta<H2, W2, 2>(f2, c, s_off[n][2], s_i0[n][2], s_spo[n][2],
                                 s_flags[n][2], w00, w10, w01, w11);
        s += use_meta<H3, W3, 1>(f3, c, s_off[n][3], s_i0[n][3], s_spo[n][3],
                                 s_flags[n][3], w00, w10, w01, w11);
        acc += s;
    }

    float inv = __fdividef(0.25f, (float)cnt + EPSF);
    out[bm * Cc + c] = acc * inv;
}

extern "C" void kernel_launch(void* const* d_in, const int* in_sizes, int n_in,
                              void* d_out, int out_size)
{
    const float* f0   = (const float*)d_in[0];
    const float* f1   = (const float*)d_in[1];
    const float* f2   = (const float*)d_in[2];
    const float* f3   = (const float*)d_in[3];
    const float* refp = (const float*)d_in[4];
    const float* l2i  = (const float*)d_in[5];
    float* out = (float*)d_out;

    feature_sampler_kernel<<<Bq * Mq, Cc>>>(f0, f1, f2, f3, refp, l2i, out);
}